// round 14
// baseline (speedup 1.0000x reference)
#include <cuda_runtime.h>
#include <cuda_fp16.h>
#include <cstdint>

#define BB 2
#define TT 2048
#define CCH 1024
#define HH 16
#define DD 64
#define MROWS (BB * TT)       // 4096
#define NEG_BIG (-1e30f)

// Scratch (half-precision working set)
__device__ __half g_qkv[(size_t)MROWS * 3 * CCH];
__device__ __half g_att[(size_t)MROWS * CCH];
__device__ __half g_xh[(size_t)MROWS * CCH];
__device__ __half g_wqkv[(size_t)CCH * 3 * CCH];
__device__ __half g_wproj[(size_t)CCH * CCH];

// ---------------------------------------------------------------------------
// Helpers
// ---------------------------------------------------------------------------
__device__ __forceinline__ uint32_t sptr(const void* p) {
    return (uint32_t)__cvta_generic_to_shared(p);
}
__device__ __forceinline__ void cpa16(uint32_t d, const void* s) {
    asm volatile("cp.async.ca.shared.global [%0], [%1], 16;" :: "r"(d), "l"(s));
}
#define CP_COMMIT() asm volatile("cp.async.commit_group;" ::)
#define CP_WAIT(N)  asm volatile("cp.async.wait_group %0;" :: "n"(N))

__device__ __forceinline__ void ldsm4(uint32_t& r0, uint32_t& r1, uint32_t& r2,
                                      uint32_t& r3, uint32_t addr) {
    asm volatile("ldmatrix.sync.aligned.m8n8.x4.shared.b16 {%0,%1,%2,%3}, [%4];"
                 : "=r"(r0), "=r"(r1), "=r"(r2), "=r"(r3) : "r"(addr));
}
__device__ __forceinline__ void ldsm4t(uint32_t& r0, uint32_t& r1, uint32_t& r2,
                                       uint32_t& r3, uint32_t addr) {
    asm volatile("ldmatrix.sync.aligned.m8n8.x4.trans.shared.b16 {%0,%1,%2,%3}, [%4];"
                 : "=r"(r0), "=r"(r1), "=r"(r2), "=r"(r3) : "r"(addr));
}
__device__ __forceinline__ void mma16816(float c[4], const uint32_t a[4],
                                         uint32_t b0, uint32_t b1) {
    asm volatile(
        "mma.sync.aligned.m16n8k16.row.col.f32.f16.f16.f32 "
        "{%0,%1,%2,%3}, {%4,%5,%6,%7}, {%8,%9}, {%0,%1,%2,%3};\n"
        : "+f"(c[0]), "+f"(c[1]), "+f"(c[2]), "+f"(c[3])
        : "r"(a[0]), "r"(a[1]), "r"(a[2]), "r"(a[3]), "r"(b0), "r"(b1));
}
__device__ __forceinline__ uint32_t h2u(__half2 h) { return *reinterpret_cast<uint32_t*>(&h); }
__device__ __forceinline__ uint32_t ex2_f16x2(uint32_t v) {
    uint32_t r;
    asm("ex2.approx.f16x2 %0, %1;" : "=r"(r) : "r"(v));
    return r;
}

// ---------------------------------------------------------------------------
// fp32 -> fp16 conversion pre-pass (single fused launch for x, Wqkv, Wproj)
// ---------------------------------------------------------------------------
__global__ void cvt_f2h3(const float* __restrict__ s0, __half* __restrict__ d0, int n0,
                         const float* __restrict__ s1, __half* __restrict__ d1, int n1,
                         const float* __restrict__ s2, __half* __restrict__ d2, int n2) {
    int i = blockIdx.x * blockDim.x + threadIdx.x;
    const float* src; __half* dst;
    if (i < n0) { src = s0; dst = d0; }
    else if (i < n0 + n1) { src = s1; dst = d1; i -= n0; }
    else if (i < n0 + n1 + n2) { src = s2; dst = d2; i -= n0 + n1; }
    else return;
    float4 v = reinterpret_cast<const float4*>(src)[i];
    __half2* d = reinterpret_cast<__half2*>(dst) + 2 * i;
    d[0] = __floats2half2_rn(v.x, v.y);
    d[1] = __floats2half2_rn(v.z, v.w);
}

// ---------------------------------------------------------------------------
// FP16 GEMM + fp32 bias.  Block 128(M) x 128(N), 256 thr (8 warps, 64x32 warp
// tiles), BK=64 (4 k16 steps between barrier pairs), 2-stage cp.async,
// 2 blocks/SM.  A smem [m][k] stride 72h; B smem [k][n] stride 136h + trans.
// ---------------------------------------------------------------------------
#define GAS 72
#define GBS 136
#define GA_TILE (128 * GAS)
#define GB_TILE (64 * GBS)
#define GEMM_SMEM ((2 * GA_TILE + 2 * GB_TILE) * 2)

__global__ __launch_bounds__(256, 2)
void gemm_f16(const __half* __restrict__ A, const __half* __restrict__ B,
              const float* __restrict__ bias, __half* __restrict__ Ch,
              float* __restrict__ Cf, int M, int N, int K) {
    extern __shared__ __half sm[];
    __half* AsB = sm;                  // [2][128][GAS]
    __half* BsB = sm + 2 * GA_TILE;    // [2][64][GBS]

    const int tid = threadIdx.x;
    const int w = tid >> 5, lane = tid & 31;
    const int g = lane >> 2, tg = lane & 3;
    const int wm = (w & 1) * 64, wn = (w >> 1) * 32;
    const int rowBase = blockIdx.y * 128;
    const int colBase = blockIdx.x * 128;

    // cp.async indices: A 128x64h = 1024 chunks (4/thr); B 64x128h = 1024 (4/thr)
    int aRow[4], aC8[4], bRow[4], bC8[4];
#pragma unroll
    for (int i = 0; i < 4; i++) {
        int idx = i * 256 + tid;
        aRow[i] = idx >> 3; aC8[i] = (idx & 7) * 8;
        bRow[i] = idx >> 4; bC8[i] = (idx & 15) * 8;
    }

    const int aLrow = lane & 15, aLk = (lane >> 4) * 8;
    const int bLk = ((lane >> 3) & 1) * 8 + (lane & 7), bLn = (lane >> 4) * 8;

    auto issue = [&](int stage, int k0) {
        __half* as = AsB + stage * GA_TILE;
        __half* bs = BsB + stage * GB_TILE;
#pragma unroll
        for (int i = 0; i < 4; i++) {
            cpa16(sptr(&as[aRow[i] * GAS + aC8[i]]),
                  &A[(size_t)(rowBase + aRow[i]) * K + k0 + aC8[i]]);
            cpa16(sptr(&bs[bRow[i] * GBS + bC8[i]]),
                  &B[(size_t)(k0 + bRow[i]) * N + colBase + bC8[i]]);
        }
        CP_COMMIT();
    };

    issue(0, 0);

    float acc[4][4][4];
#pragma unroll
    for (int mt = 0; mt < 4; mt++)
#pragma unroll
        for (int nt = 0; nt < 4; nt++)
#pragma unroll
            for (int r = 0; r < 4; r++) acc[mt][nt][r] = 0.f;

    const int KT = K >> 6;
    for (int t = 0; t < KT; t++) {
        const int cur = t & 1;
        if (t + 1 < KT) { issue(cur ^ 1, (t + 1) * 64); CP_WAIT(1); }
        else            { CP_WAIT(0); }
        __syncthreads();

        const __half* as = AsB + cur * GA_TILE;
        const __half* bs = BsB + cur * GB_TILE;
#pragma unroll
        for (int s = 0; s < 4; s++) {
            const int k16 = s * 16;
            uint32_t a[4][4];
#pragma unroll
            for (int mt = 0; mt < 4; mt++)
                ldsm4(a[mt][0], a[mt][1], a[mt][2], a[mt][3],
                      sptr(&as[(wm + mt * 16 + aLrow) * GAS + k16 + aLk]));
#pragma unroll
            for (int ntp = 0; ntp < 2; ntp++) {
                uint32_t b0e, b1e, b0o, b1o;
                ldsm4t(b0e, b1e, b0o, b1o,
                       sptr(&bs[(k16 + bLk) * GBS + wn + ntp * 16 + bLn]));
#pragma unroll
                for (int mt = 0; mt < 4; mt++) {
                    mma16816(acc[mt][2 * ntp], a[mt], b0e, b1e);
                    mma16816(acc[mt][2 * ntp + 1], a[mt], b0o, b1o);
                }
            }
        }
        __syncthreads();
    }

    // epilogue
#pragma unroll
    for (int mt = 0; mt < 4; mt++) {
        const int r0 = rowBase + wm + mt * 16 + g;
#pragma unroll
        for (int nt = 0; nt < 4; nt++) {
            const int col = colBase + wn + nt * 8 + tg * 2;
            const float bx = bias[col], by = bias[col + 1];
            float v00 = acc[mt][nt][0] + bx, v01 = acc[mt][nt][1] + by;
            float v10 = acc[mt][nt][2] + bx, v11 = acc[mt][nt][3] + by;
            if (Cf) {
                float2 o0 = {v00, v01}, o1 = {v10, v11};
                *reinterpret_cast<float2*>(&Cf[(size_t)r0 * N + col]) = o0;
                *reinterpret_cast<float2*>(&Cf[(size_t)(r0 + 8) * N + col]) = o1;
            } else {
                *reinterpret_cast<__half2*>(&Ch[(size_t)r0 * N + col]) =
                    __floats2half2_rn(v00, v01);
                *reinterpret_cast<__half2*>(&Ch[(size_t)(r0 + 8) * N + col]) =
                    __floats2half2_rn(v10, v11);
            }
        }
    }
}

// ---------------------------------------------------------------------------
// FP16 flash attention (causal).  256 thr (8 warps), BQ=128 (16 rows/warp),
// BKV=64, 3-stage cp.async KV ring, 2 blocks/SM.  log2-domain scores,
// f16x2 exp2 softmax (P produced directly as PV A-fragments), vote-skipped
// O rescale.   (unchanged from R12)
// ---------------------------------------------------------------------------
#define AS 72   // smem row stride in halves (144B)
#define KV_TILE (64 * AS)
#define ATT_SMEM ((128 * AS + 3 * 2 * KV_TILE) * 2)

__global__ __launch_bounds__(256, 2)
void attn_f16(const __half* __restrict__ qkv, __half* __restrict__ out) {
    extern __shared__ __half smh[];
    __half* Qs = smh;                        // [128][AS]
    __half* KVs = smh + 128 * AS;            // [3][2][64][AS]

    const int qb = (gridDim.x - 1) - blockIdx.x;
    const int h = blockIdx.y, b = blockIdx.z;
    const int tid = threadIdx.x;
    const int w = tid >> 5, lane = tid & 31;
    const int g = lane >> 2, tg = lane & 3;

    const int aLrow = lane & 15, aLk = (lane >> 4) * 8;                        // Q
    const int kLn = ((lane >> 4) << 3) + (lane & 7), kLk = ((lane >> 3) & 1) * 8;  // K
    const int vLk = ((lane >> 3) & 1) * 8 + (lane & 7), vLn = (lane >> 4) * 8;     // V

    int kvRow[2], kvC8[2];
#pragma unroll
    for (int i = 0; i < 2; i++) {
        int idx = i * 256 + tid;
        kvRow[i] = idx >> 3; kvC8[i] = (idx & 7) * 8;
    }

    auto issueKV = [&](int stage, int kt) {
        __half* Ks = KVs + stage * 2 * KV_TILE;
        __half* Vs = Ks + KV_TILE;
#pragma unroll
        for (int i = 0; i < 2; i++) {
            const size_t gofs =
                ((size_t)(b * TT + kt * 64 + kvRow[i])) * (3 * CCH) + h * DD + kvC8[i];
            cpa16(sptr(&Ks[kvRow[i] * AS + kvC8[i]]), &qkv[gofs + CCH]);
            cpa16(sptr(&Vs[kvRow[i] * AS + kvC8[i]]), &qkv[gofs + 2 * CCH]);
        }
        CP_COMMIT();
    };

    const int ktmax = 2 * qb + 1;
    issueKV(0, 0);
    issueKV(1, 1);

#pragma unroll
    for (int i = 0; i < 4; i++) {
        const int idx = i * 256 + tid;
        const int row = idx >> 3, c8 = (idx & 7) * 8;
        const size_t gofs = ((size_t)(b * TT + qb * 128 + row)) * (3 * CCH) + h * DD + c8;
        *reinterpret_cast<uint4*>(&Qs[row * AS + c8]) =
            *reinterpret_cast<const uint4*>(&qkv[gofs]);
    }
    __syncthreads();

    // Q fragments; scale = 1/8 * log2(e)
    uint32_t qf[4][4];
    {
        const __half2 sc = __float2half2_rn(0.125f * 1.44269504f);
#pragma unroll
        for (int s = 0; s < 4; s++) {
            uint32_t r0, r1, r2, r3;
            ldsm4(r0, r1, r2, r3, sptr(&Qs[(w * 16 + aLrow) * AS + s * 16 + aLk]));
            qf[s][0] = h2u(__hmul2(*reinterpret_cast<__half2*>(&r0), sc));
            qf[s][1] = h2u(__hmul2(*reinterpret_cast<__half2*>(&r1), sc));
            qf[s][2] = h2u(__hmul2(*reinterpret_cast<__half2*>(&r2), sc));
            qf[s][3] = h2u(__hmul2(*reinterpret_cast<__half2*>(&r3), sc));
        }
    }

    float O[8][4];
#pragma unroll
    for (int nt = 0; nt < 8; nt++)
#pragma unroll
        for (int r = 0; r < 4; r++) O[nt][r] = 0.f;
    float mx0 = NEG_BIG, mx1 = NEG_BIG, l0 = 0.f, l1 = 0.f;

    const int qmin = qb * 128 + w * 16;

    int stage = 0;
    for (int kt = 0; kt <= ktmax; kt++) {
        if (kt + 2 <= ktmax) CP_WAIT(1); else CP_WAIT(0);
        __syncthreads();
        if (kt + 2 <= ktmax) {
            int ns = stage + 2; if (ns >= 3) ns -= 3;
            issueKV(ns, kt + 2);
        }

        const __half* Ks = KVs + stage * 2 * KV_TILE;
        const __half* Vs = Ks + KV_TILE;

        int rem = ((qmin + 15 - kt * 64) >> 3) + 1;
        const int ntc = rem < 8 ? rem : 8;
        if (ntc > 0) {
            const bool needmask = (kt * 64 + 63 > qmin);

            float s[8][4];
#pragma unroll
            for (int nt = 0; nt < 8; nt++)
#pragma unroll
                for (int r = 0; r < 4; r++) s[nt][r] = 0.f;

#pragma unroll
            for (int ks = 0; ks < 4; ks++) {
#pragma unroll
                for (int ntp = 0; ntp < 4; ntp++) {
                    if (2 * ntp < ntc) {
                        uint32_t b0e, b1e, b0o, b1o;
                        ldsm4(b0e, b1e, b0o, b1o,
                              sptr(&Ks[(ntp * 16 + kLn) * AS + ks * 16 + kLk]));
                        mma16816(s[2 * ntp], qf[ks], b0e, b1e);
                        mma16816(s[2 * ntp + 1], qf[ks], b0o, b1o);
                    }
                }
            }

            if (needmask) {
                const int r0 = qmin + g, r1 = r0 + 8;
#pragma unroll
                for (int nt = 0; nt < 8; nt++) {
                    if (nt < ntc) {
                        const int c0 = kt * 64 + nt * 8 + tg * 2, c1 = c0 + 1;
                        if (c0 > r0) s[nt][0] = NEG_BIG;
                        if (c1 > r0) s[nt][1] = NEG_BIG;
                        if (c0 > r1) s[nt][2] = NEG_BIG;
                        if (c1 > r1) s[nt][3] = NEG_BIG;
                    }
                }
            }

            float mt0 = NEG_BIG, mt1 = NEG_BIG;
#pragma unroll
            for (int nt = 0; nt < 8; nt++) {
                if (nt < ntc) {
                    mt0 = fmaxf(mt0, fmaxf(s[nt][0], s[nt][1]));
                    mt1 = fmaxf(mt1, fmaxf(s[nt][2], s[nt][3]));
                }
            }
            mt0 = fmaxf(mt0, __shfl_xor_sync(0xffffffffu, mt0, 1));
            mt0 = fmaxf(mt0, __shfl_xor_sync(0xffffffffu, mt0, 2));
            mt1 = fmaxf(mt1, __shfl_xor_sync(0xffffffffu, mt1, 1));
            mt1 = fmaxf(mt1, __shfl_xor_sync(0xffffffffu, mt1, 2));
            const float nm0 = fmaxf(mx0, mt0), nm1 = fmaxf(mx1, mt1);
            const bool upd = (nm0 > mx0) || (nm1 > mx1);
            const float c0 = exp2f(mx0 - nm0), c1 = exp2f(mx1 - nm1);

            uint32_t P0[8], P1[8];
            const __half2 nmh0 = __float2half2_rn(nm0);
            const __half2 nmh1 = __float2half2_rn(nm1);
            float rs0 = 0.f, rs1 = 0.f;
#pragma unroll
            for (int nt = 0; nt < 8; nt++) {
                if (nt < ntc) {
                    __half2 a0 = __hsub2(__floats2half2_rn(s[nt][0], s[nt][1]), nmh0);
                    __half2 a1 = __hsub2(__floats2half2_rn(s[nt][2], s[nt][3]), nmh1);
                    uint32_t p0 = ex2_f16x2(h2u(a0));
                    uint32_t p1 = ex2_f16x2(h2u(a1));
                    P0[nt] = p0; P1[nt] = p1;
                    float2 f0 = __half22float2(*reinterpret_cast<__half2*>(&p0));
                    float2 f1 = __half22float2(*reinterpret_cast<__half2*>(&p1));
                    rs0 += f0.x + f0.y;
                    rs1 += f1.x + f1.y;
                } else {
                    P0[nt] = 0u; P1[nt] = 0u;
                }
            }
            rs0 += __shfl_xor_sync(0xffffffffu, rs0, 1);
            rs0 += __shfl_xor_sync(0xffffffffu, rs0, 2);
            rs1 += __shfl_xor_sync(0xffffffffu, rs1, 1);
            rs1 += __shfl_xor_sync(0xffffffffu, rs1, 2);
            l0 = l0 * c0 + rs0;
            l1 = l1 * c1 + rs1;
            mx0 = nm0; mx1 = nm1;

            if (__any_sync(0xffffffffu, upd)) {
#pragma unroll
                for (int nt = 0; nt < 8; nt++) {
                    O[nt][0] *= c0; O[nt][1] *= c0;
                    O[nt][2] *= c1; O[nt][3] *= c1;
                }
            }

            const int spc = (ntc + 1) >> 1;
#pragma unroll
            for (int sp = 0; sp < 4; sp++) {
                if (sp < spc) {
                    uint32_t pa[4];
                    pa[0] = P0[2 * sp];
                    pa[1] = P1[2 * sp];
                    pa[2] = P0[2 * sp + 1];
                    pa[3] = P1[2 * sp + 1];
#pragma unroll
                    for (int ntp = 0; ntp < 4; ntp++) {
                        uint32_t b0e, b1e, b0o, b1o;
                        ldsm4t(b0e, b1e, b0o, b1o,
                               sptr(&Vs[(sp * 16 + vLk) * AS + ntp * 16 + vLn]));
                        mma16816(O[2 * ntp], pa, b0e, b1e);
                        mma16816(O[2 * ntp + 1], pa, b0o, b1o);
                    }
                }
            }
        }
        if (++stage == 3) stage = 0;
    }

    const float inv0 = 1.f / l0, inv1 = 1.f / l1;
    const int row0 = qb * 128 + w * 16 + g;
#pragma unroll
    for (int nt = 0; nt < 8; nt++) {
        const int col = h * DD + nt * 8 + tg * 2;
        *reinterpret_cast<__half2*>(&out[(size_t)(b * TT + row0) * CCH + col]) =
            __floats2half2_rn(O[nt][0] * inv0, O[nt][1] * inv0);
        *reinterpret_cast<__half2*>(&out[(size_t)(b * TT + row0 + 8) * CCH + col]) =
            __floats2half2_rn(O[nt][2] * inv1, O[nt][3] * inv1);
    }
}

// ---------------------------------------------------------------------------
extern "C" void kernel_launch(void* const* d_in, const int* in_sizes, int n_in,
                              void* d_out, int out_size) {
    const float* x     = (const float*)d_in[0];
    const float* Wqkv  = (const float*)d_in[1];
    const float* bqkv  = (const float*)d_in[2];
    const float* Wproj = (const float*)d_in[3];
    const float* bproj = (const float*)d_in[4];
    float* out = (float*)d_out;

    __half *qkv, *att, *xh, *wqkv, *wproj;
    cudaGetSymbolAddress((void**)&qkv, g_qkv);
    cudaGetSymbolAddress((void**)&att, g_att);
    cudaGetSymbolAddress((void**)&xh, g_xh);
    cudaGetSymbolAddress((void**)&wqkv, g_wqkv);
    cudaGetSymbolAddress((void**)&wproj, g_wproj);

    // 0) fused fp32 -> fp16 pre-pass
    {
        int n4x = MROWS * CCH / 4;
        int n4q = CCH * 3 * CCH / 4;
        int n4p = CCH * CCH / 4;
        int total = n4x + n4q + n4p;
        cvt_f2h3<<<(total + 255) / 256, 256>>>(x, xh, n4x, Wqkv, wqkv, n4q,
                                               Wproj, wproj, n4p);
    }
    // 1) QKV projection -> half
    {
        cudaFuncSetAttribute(gemm_f16, cudaFuncAttributeMaxDynamicSharedMemorySize,
                             GEMM_SMEM);
        dim3 grid(3 * CCH / 128, MROWS / 128);
        gemm_f16<<<grid, 256, GEMM_SMEM>>>(xh, wqkv, bqkv, qkv, nullptr,
                                           MROWS, 3 * CCH, CCH);
    }
    // 2) Flash attention -> half
    {
        cudaFuncSetAttribute(attn_f16, cudaFuncAttributeMaxDynamicSharedMemorySize,
                             ATT_SMEM);
        dim3 grid(TT / 128, HH, BB);
        attn_f16<<<grid, 256, ATT_SMEM>>>(qkv, att);
    }
    // 3) Output projection -> fp32
    {
        dim3 grid(CCH / 128, MROWS / 128);
        gemm_f16<<<grid, 256, GEMM_SMEM>>>(att, wproj, bproj, nullptr, out,
                                           MROWS, CCH, CCH);
    }
}

// round 15
// speedup vs baseline: 1.4512x; 1.4512x over previous
#include <cuda_runtime.h>
#include <cuda_fp16.h>
#include <cstdint>

#define BB 2
#define TT 2048
#define CCH 1024
#define HH 16
#define DD 64
#define MROWS (BB * TT)       // 4096
#define NEG_BIG (-1e30f)

// Scratch (half-precision working set)
__device__ __half g_qkv[(size_t)MROWS * 3 * CCH];
__device__ __half g_att[(size_t)MROWS * CCH];
__device__ __half g_xh[(size_t)MROWS * CCH];
__device__ __half g_wqkv[(size_t)CCH * 3 * CCH];
__device__ __half g_wproj[(size_t)CCH * CCH];

// ---------------------------------------------------------------------------
// Helpers
// ---------------------------------------------------------------------------
__device__ __forceinline__ uint32_t sptr(const void* p) {
    return (uint32_t)__cvta_generic_to_shared(p);
}
__device__ __forceinline__ void cpa16(uint32_t d, const void* s) {
    asm volatile("cp.async.ca.shared.global [%0], [%1], 16;" :: "r"(d), "l"(s));
}
#define CP_COMMIT() asm volatile("cp.async.commit_group;" ::)
#define CP_WAIT(N)  asm volatile("cp.async.wait_group %0;" :: "n"(N))

__device__ __forceinline__ void ldsm4(uint32_t& r0, uint32_t& r1, uint32_t& r2,
                                      uint32_t& r3, uint32_t addr) {
    asm volatile("ldmatrix.sync.aligned.m8n8.x4.shared.b16 {%0,%1,%2,%3}, [%4];"
                 : "=r"(r0), "=r"(r1), "=r"(r2), "=r"(r3) : "r"(addr));
}
__device__ __forceinline__ void ldsm4t(uint32_t& r0, uint32_t& r1, uint32_t& r2,
                                       uint32_t& r3, uint32_t addr) {
    asm volatile("ldmatrix.sync.aligned.m8n8.x4.trans.shared.b16 {%0,%1,%2,%3}, [%4];"
                 : "=r"(r0), "=r"(r1), "=r"(r2), "=r"(r3) : "r"(addr));
}
__device__ __forceinline__ void mma16816(float c[4], const uint32_t a[4],
                                         uint32_t b0, uint32_t b1) {
    asm volatile(
        "mma.sync.aligned.m16n8k16.row.col.f32.f16.f16.f32 "
        "{%0,%1,%2,%3}, {%4,%5,%6,%7}, {%8,%9}, {%0,%1,%2,%3};\n"
        : "+f"(c[0]), "+f"(c[1]), "+f"(c[2]), "+f"(c[3])
        : "r"(a[0]), "r"(a[1]), "r"(a[2]), "r"(a[3]), "r"(b0), "r"(b1));
}
__device__ __forceinline__ uint32_t h2u(__half2 h) { return *reinterpret_cast<uint32_t*>(&h); }
__device__ __forceinline__ uint32_t ex2_f16x2(uint32_t v) {
    uint32_t r;
    asm("ex2.approx.f16x2 %0, %1;" : "=r"(r) : "r"(v));
    return r;
}

// ---------------------------------------------------------------------------
// fp32 -> fp16 conversion pre-pass (single fused launch for x, Wqkv, Wproj)
// ---------------------------------------------------------------------------
__global__ void cvt_f2h3(const float* __restrict__ s0, __half* __restrict__ d0, int n0,
                         const float* __restrict__ s1, __half* __restrict__ d1, int n1,
                         const float* __restrict__ s2, __half* __restrict__ d2, int n2) {
    int i = blockIdx.x * blockDim.x + threadIdx.x;
    const float* src; __half* dst;
    if (i < n0) { src = s0; dst = d0; }
    else if (i < n0 + n1) { src = s1; dst = d1; i -= n0; }
    else if (i < n0 + n1 + n2) { src = s2; dst = d2; i -= n0 + n1; }
    else return;
    float4 v = reinterpret_cast<const float4*>(src)[i];
    __half2* d = reinterpret_cast<__half2*>(dst) + 2 * i;
    d[0] = __floats2half2_rn(v.x, v.y);
    d[1] = __floats2half2_rn(v.z, v.w);
}

// ---------------------------------------------------------------------------
// FP16 GEMM + fp32 bias.  Block 128(M) x 128(N), 256 thr (8 warps, 64x32 warp
// tiles), BK=32, 4-stage cp.async ring, ONE __syncthreads per K-iter,
// 2 blocks/SM.  A smem [m][k] stride 40h; B smem [k][n] stride 136h + trans.
// ---------------------------------------------------------------------------
#define GAS 40
#define GBS 136
#define GA_TILE (128 * GAS)
#define GB_TILE (32 * GBS)
#define NSTG 4
#define GEMM_SMEM ((NSTG * GA_TILE + NSTG * GB_TILE) * 2)

__global__ __launch_bounds__(256, 2)
void gemm_f16(const __half* __restrict__ A, const __half* __restrict__ B,
              const float* __restrict__ bias, __half* __restrict__ Ch,
              float* __restrict__ Cf, int M, int N, int K) {
    extern __shared__ __half sm[];
    __half* AsB = sm;                     // [4][128][GAS]
    __half* BsB = sm + NSTG * GA_TILE;    // [4][32][GBS]

    const int tid = threadIdx.x;
    const int w = tid >> 5, lane = tid & 31;
    const int g = lane >> 2, tg = lane & 3;
    const int wm = (w & 1) * 64, wn = (w >> 1) * 32;
    const int rowBase = blockIdx.y * 128;
    const int colBase = blockIdx.x * 128;

    int aRow[2], aC8[2], bRow[2], bC8[2];
#pragma unroll
    for (int i = 0; i < 2; i++) {
        int idx = i * 256 + tid;
        aRow[i] = idx >> 2; aC8[i] = (idx & 3) * 8;
        bRow[i] = idx >> 4; bC8[i] = (idx & 15) * 8;
    }

    const int aLrow = lane & 15, aLk = (lane >> 4) * 8;
    const int bLk = ((lane >> 3) & 1) * 8 + (lane & 7), bLn = (lane >> 4) * 8;

    auto issue = [&](int stage, int k0) {
        __half* as = AsB + stage * GA_TILE;
        __half* bs = BsB + stage * GB_TILE;
#pragma unroll
        for (int i = 0; i < 2; i++) {
            cpa16(sptr(&as[aRow[i] * GAS + aC8[i]]),
                  &A[(size_t)(rowBase + aRow[i]) * K + k0 + aC8[i]]);
            cpa16(sptr(&bs[bRow[i] * GBS + bC8[i]]),
                  &B[(size_t)(k0 + bRow[i]) * N + colBase + bC8[i]]);
        }
        CP_COMMIT();
    };

    const int KT = K >> 5;       // 32
    issue(0, 0);
    issue(1, 32);
    issue(2, 64);

    float acc[4][4][4];
#pragma unroll
    for (int mt = 0; mt < 4; mt++)
#pragma unroll
        for (int nt = 0; nt < 4; nt++)
#pragma unroll
            for (int r = 0; r < 4; r++) acc[mt][nt][r] = 0.f;

    for (int t = 0; t < KT; t++) {
        if (t + 3 < KT) CP_WAIT(2); else CP_WAIT(0);
        __syncthreads();
        if (t + 3 < KT) issue((t + 3) & (NSTG - 1), (t + 3) * 32);

        const __half* as = AsB + (t & (NSTG - 1)) * GA_TILE;
        const __half* bs = BsB + (t & (NSTG - 1)) * GB_TILE;
#pragma unroll
        for (int s = 0; s < 2; s++) {
            const int k16 = s * 16;
            uint32_t a[4][4];
#pragma unroll
            for (int mt = 0; mt < 4; mt++)
                ldsm4(a[mt][0], a[mt][1], a[mt][2], a[mt][3],
                      sptr(&as[(wm + mt * 16 + aLrow) * GAS + k16 + aLk]));
#pragma unroll
            for (int ntp = 0; ntp < 2; ntp++) {
                uint32_t b0e, b1e, b0o, b1o;
                ldsm4t(b0e, b1e, b0o, b1o,
                       sptr(&bs[(k16 + bLk) * GBS + wn + ntp * 16 + bLn]));
#pragma unroll
                for (int mt = 0; mt < 4; mt++) {
                    mma16816(acc[mt][2 * ntp], a[mt], b0e, b1e);
                    mma16816(acc[mt][2 * ntp + 1], a[mt], b0o, b1o);
                }
            }
        }
    }

    // epilogue
#pragma unroll
    for (int mt = 0; mt < 4; mt++) {
        const int r0 = rowBase + wm + mt * 16 + g;
#pragma unroll
        for (int nt = 0; nt < 4; nt++) {
            const int col = colBase + wn + nt * 8 + tg * 2;
            const float bx = bias[col], by = bias[col + 1];
            float v00 = acc[mt][nt][0] + bx, v01 = acc[mt][nt][1] + by;
            float v10 = acc[mt][nt][2] + bx, v11 = acc[mt][nt][3] + by;
            if (Cf) {
                float2 o0 = {v00, v01}, o1 = {v10, v11};
                *reinterpret_cast<float2*>(&Cf[(size_t)r0 * N + col]) = o0;
                *reinterpret_cast<float2*>(&Cf[(size_t)(r0 + 8) * N + col]) = o1;
            } else {
                *reinterpret_cast<__half2*>(&Ch[(size_t)r0 * N + col]) =
                    __floats2half2_rn(v00, v01);
                *reinterpret_cast<__half2*>(&Ch[(size_t)(r0 + 8) * N + col]) =
                    __floats2half2_rn(v10, v11);
            }
        }
    }
}

// ---------------------------------------------------------------------------
// FP16 flash attention (causal).  256 thr (8 warps), BQ=128 (16 rows/warp),
// BKV=64, 3-stage cp.async KV ring, 2 blocks/SM.  log2-domain scores,
// f16x2 exp2 softmax (P produced directly as PV A-fragments), vote-skipped
// O rescale.   (unchanged from the 215.1 config)
// ---------------------------------------------------------------------------
#define AS 72   // smem row stride in halves (144B)
#define KV_TILE (64 * AS)
#define ATT_SMEM ((128 * AS + 3 * 2 * KV_TILE) * 2)

__global__ __launch_bounds__(256, 2)
void attn_f16(const __half* __restrict__ qkv, __half* __restrict__ out) {
    extern __shared__ __half smh[];
    __half* Qs = smh;                        // [128][AS]
    __half* KVs = smh + 128 * AS;            // [3][2][64][AS]

    const int qb = (gridDim.x - 1) - blockIdx.x;
    const int h = blockIdx.y, b = blockIdx.z;
    const int tid = threadIdx.x;
    const int w = tid >> 5, lane = tid & 31;
    const int g = lane >> 2, tg = lane & 3;

    const int aLrow = lane & 15, aLk = (lane >> 4) * 8;                        // Q
    const int kLn = ((lane >> 4) << 3) + (lane & 7), kLk = ((lane >> 3) & 1) * 8;  // K
    const int vLk = ((lane >> 3) & 1) * 8 + (lane & 7), vLn = (lane >> 4) * 8;     // V

    int kvRow[2], kvC8[2];
#pragma unroll
    for (int i = 0; i < 2; i++) {
        int idx = i * 256 + tid;
        kvRow[i] = idx >> 3; kvC8[i] = (idx & 7) * 8;
    }

    auto issueKV = [&](int stage, int kt) {
        __half* Ks = KVs + stage * 2 * KV_TILE;
        __half* Vs = Ks + KV_TILE;
#pragma unroll
        for (int i = 0; i < 2; i++) {
            const size_t gofs =
                ((size_t)(b * TT + kt * 64 + kvRow[i])) * (3 * CCH) + h * DD + kvC8[i];
            cpa16(sptr(&Ks[kvRow[i] * AS + kvC8[i]]), &qkv[gofs + CCH]);
            cpa16(sptr(&Vs[kvRow[i] * AS + kvC8[i]]), &qkv[gofs + 2 * CCH]);
        }
        CP_COMMIT();
    };

    const int ktmax = 2 * qb + 1;
    issueKV(0, 0);
    issueKV(1, 1);

#pragma unroll
    for (int i = 0; i < 4; i++) {
        const int idx = i * 256 + tid;
        const int row = idx >> 3, c8 = (idx & 7) * 8;
        const size_t gofs = ((size_t)(b * TT + qb * 128 + row)) * (3 * CCH) + h * DD + c8;
        *reinterpret_cast<uint4*>(&Qs[row * AS + c8]) =
            *reinterpret_cast<const uint4*>(&qkv[gofs]);
    }
    __syncthreads();

    // Q fragments; scale = 1/8 * log2(e)
    uint32_t qf[4][4];
    {
        const __half2 sc = __float2half2_rn(0.125f * 1.44269504f);
#pragma unroll
        for (int s = 0; s < 4; s++) {
            uint32_t r0, r1, r2, r3;
            ldsm4(r0, r1, r2, r3, sptr(&Qs[(w * 16 + aLrow) * AS + s * 16 + aLk]));
            qf[s][0] = h2u(__hmul2(*reinterpret_cast<__half2*>(&r0), sc));
            qf[s][1] = h2u(__hmul2(*reinterpret_cast<__half2*>(&r1), sc));
            qf[s][2] = h2u(__hmul2(*reinterpret_cast<__half2*>(&r2), sc));
            qf[s][3] = h2u(__hmul2(*reinterpret_cast<__half2*>(&r3), sc));
        }
    }

    float O[8][4];
#pragma unroll
    for (int nt = 0; nt < 8; nt++)
#pragma unroll
        for (int r = 0; r < 4; r++) O[nt][r] = 0.f;
    float mx0 = NEG_BIG, mx1 = NEG_BIG, l0 = 0.f, l1 = 0.f;

    const int qmin = qb * 128 + w * 16;

    int stage = 0;
    for (int kt = 0; kt <= ktmax; kt++) {
        if (kt + 2 <= ktmax) CP_WAIT(1); else CP_WAIT(0);
        __syncthreads();
        if (kt + 2 <= ktmax) {
            int ns = stage + 2; if (ns >= 3) ns -= 3;
            issueKV(ns, kt + 2);
        }

        const __half* Ks = KVs + stage * 2 * KV_TILE;
        const __half* Vs = Ks + KV_TILE;

        int rem = ((qmin + 15 - kt * 64) >> 3) + 1;
        const int ntc = rem < 8 ? rem : 8;
        if (ntc > 0) {
            const bool needmask = (kt * 64 + 63 > qmin);

            float s[8][4];
#pragma unroll
            for (int nt = 0; nt < 8; nt++)
#pragma unroll
                for (int r = 0; r < 4; r++) s[nt][r] = 0.f;

#pragma unroll
            for (int ks = 0; ks < 4; ks++) {
#pragma unroll
                for (int ntp = 0; ntp < 4; ntp++) {
                    if (2 * ntp < ntc) {
                        uint32_t b0e, b1e, b0o, b1o;
                        ldsm4(b0e, b1e, b0o, b1o,
                              sptr(&Ks[(ntp * 16 + kLn) * AS + ks * 16 + kLk]));
                        mma16816(s[2 * ntp], qf[ks], b0e, b1e);
                        mma16816(s[2 * ntp + 1], qf[ks], b0o, b1o);
                    }
                }
            }

            if (needmask) {
                const int r0 = qmin + g, r1 = r0 + 8;
#pragma unroll
                for (int nt = 0; nt < 8; nt++) {
                    if (nt < ntc) {
                        const int c0 = kt * 64 + nt * 8 + tg * 2, c1 = c0 + 1;
                        if (c0 > r0) s[nt][0] = NEG_BIG;
                        if (c1 > r0) s[nt][1] = NEG_BIG;
                        if (c0 > r1) s[nt][2] = NEG_BIG;
                        if (c1 > r1) s[nt][3] = NEG_BIG;
                    }
                }
            }

            float mt0 = NEG_BIG, mt1 = NEG_BIG;
#pragma unroll
            for (int nt = 0; nt < 8; nt++) {
                if (nt < ntc) {
                    mt0 = fmaxf(mt0, fmaxf(s[nt][0], s[nt][1]));
                    mt1 = fmaxf(mt1, fmaxf(s[nt][2], s[nt][3]));
                }
            }
            mt0 = fmaxf(mt0, __shfl_xor_sync(0xffffffffu, mt0, 1));
            mt0 = fmaxf(mt0, __shfl_xor_sync(0xffffffffu, mt0, 2));
            mt1 = fmaxf(mt1, __shfl_xor_sync(0xffffffffu, mt1, 1));
            mt1 = fmaxf(mt1, __shfl_xor_sync(0xffffffffu, mt1, 2));
            const float nm0 = fmaxf(mx0, mt0), nm1 = fmaxf(mx1, mt1);
            const bool upd = (nm0 > mx0) || (nm1 > mx1);
            const float c0 = exp2f(mx0 - nm0), c1 = exp2f(mx1 - nm1);

            uint32_t P0[8], P1[8];
            const __half2 nmh0 = __float2half2_rn(nm0);
            const __half2 nmh1 = __float2half2_rn(nm1);
            float rs0 = 0.f, rs1 = 0.f;
#pragma unroll
            for (int nt = 0; nt < 8; nt++) {
                if (nt < ntc) {
                    __half2 a0 = __hsub2(__floats2half2_rn(s[nt][0], s[nt][1]), nmh0);
                    __half2 a1 = __hsub2(__floats2half2_rn(s[nt][2], s[nt][3]), nmh1);
                    uint32_t p0 = ex2_f16x2(h2u(a0));
                    uint32_t p1 = ex2_f16x2(h2u(a1));
                    P0[nt] = p0; P1[nt] = p1;
                    float2 f0 = __half22float2(*reinterpret_cast<__half2*>(&p0));
                    float2 f1 = __half22float2(*reinterpret_cast<__half2*>(&p1));
                    rs0 += f0.x + f0.y;
                    rs1 += f1.x + f1.y;
                } else {
                    P0[nt] = 0u; P1[nt] = 0u;
                }
            }
            rs0 += __shfl_xor_sync(0xffffffffu, rs0, 1);
            rs0 += __shfl_xor_sync(0xffffffffu, rs0, 2);
            rs1 += __shfl_xor_sync(0xffffffffu, rs1, 1);
            rs1 += __shfl_xor_sync(0xffffffffu, rs1, 2);
            l0 = l0 * c0 + rs0;
            l1 = l1 * c1 + rs1;
            mx0 = nm0; mx1 = nm1;

            if (__any_sync(0xffffffffu, upd)) {
#pragma unroll
                for (int nt = 0; nt < 8; nt++) {
                    O[nt][0] *= c0; O[nt][1] *= c0;
                    O[nt][2] *= c1; O[nt][3] *= c1;
                }
            }

            const int spc = (ntc + 1) >> 1;
#pragma unroll
            for (int sp = 0; sp < 4; sp++) {
                if (sp < spc) {
                    uint32_t pa[4];
                    pa[0] = P0[2 * sp];
                    pa[1] = P1[2 * sp];
                    pa[2] = P0[2 * sp + 1];
                    pa[3] = P1[2 * sp + 1];
#pragma unroll
                    for (int ntp = 0; ntp < 4; ntp++) {
                        uint32_t b0e, b1e, b0o, b1o;
                        ldsm4t(b0e, b1e, b0o, b1o,
                               sptr(&Vs[(sp * 16 + vLk) * AS + ntp * 16 + vLn]));
                        mma16816(O[2 * ntp], pa, b0e, b1e);
                        mma16816(O[2 * ntp + 1], pa, b0o, b1o);
                    }
                }
            }
        }
        if (++stage == 3) stage = 0;
    }

    const float inv0 = 1.f / l0, inv1 = 1.f / l1;
    const int row0 = qb * 128 + w * 16 + g;
#pragma unroll
    for (int nt = 0; nt < 8; nt++) {
        const int col = h * DD + nt * 8 + tg * 2;
        *reinterpret_cast<__half2*>(&out[(size_t)(b * TT + row0) * CCH + col]) =
            __floats2half2_rn(O[nt][0] * inv0, O[nt][1] * inv0);
        *reinterpret_cast<__half2*>(&out[(size_t)(b * TT + row0 + 8) * CCH + col]) =
            __floats2half2_rn(O[nt][2] * inv1, O[nt][3] * inv1);
    }
}

// ---------------------------------------------------------------------------
extern "C" void kernel_launch(void* const* d_in, const int* in_sizes, int n_in,
                              void* d_out, int out_size) {
    const float* x     = (const float*)d_in[0];
    const float* Wqkv  = (const float*)d_in[1];
    const float* bqkv  = (const float*)d_in[2];
    const float* Wproj = (const float*)d_in[3];
    const float* bproj = (const float*)d_in[4];
    float* out = (float*)d_out;

    __half *qkv, *att, *xh, *wqkv, *wproj;
    cudaGetSymbolAddress((void**)&qkv, g_qkv);
    cudaGetSymbolAddress((void**)&att, g_att);
    cudaGetSymbolAddress((void**)&xh, g_xh);
    cudaGetSymbolAddress((void**)&wqkv, g_wqkv);
    cudaGetSymbolAddress((void**)&wproj, g_wproj);

    // 0) fused fp32 -> fp16 pre-pass
    {
        int n4x = MROWS * CCH / 4;
        int n4q = CCH * 3 * CCH / 4;
        int n4p = CCH * CCH / 4;
        int total = n4x + n4q + n4p;
        cvt_f2h3<<<(total + 255) / 256, 256>>>(x, xh, n4x, Wqkv, wqkv, n4q,
                                               Wproj, wproj, n4p);
    }
    // 1) QKV projection -> half
    {
        cudaFuncSetAttribute(gemm_f16, cudaFuncAttributeMaxDynamicSharedMemorySize,
                             GEMM_SMEM);
        dim3 grid(3 * CCH / 128, MROWS / 128);
        gemm_f16<<<grid, 256, GEMM_SMEM>>>(xh, wqkv, bqkv, qkv, nullptr,
                                           MROWS, 3 * CCH, CCH);
    }
    // 2) Flash attention -> half
    {
        cudaFuncSetAttribute(attn_f16, cudaFuncAttributeMaxDynamicSharedMemorySize,
                             ATT_SMEM);
        dim3 grid(TT / 128, HH, BB);
        attn_f16<<<grid, 256, ATT_SMEM>>>(qkv, att);
    }
    // 3) Output projection -> fp32
    {
        dim3 grid(CCH / 128, MROWS / 128);
        gemm_f16<<<grid, 256, GEMM_SMEM>>>(att, wproj, bproj, nullptr, out,
                                           MROWS, CCH, CCH);
    }
}

// round 16
// speedup vs baseline: 1.4774x; 1.0180x over previous
#include <cuda_runtime.h>
#include <cuda_fp16.h>
#include <cstdint>

#define BB 2
#define TT 2048
#define CCH 1024
#define HH 16
#define DD 64
#define MROWS (BB * TT)       // 4096
#define NEG_BIG (-1e30f)

// Scratch (half-precision working set)
__device__ __half g_qkv[(size_t)MROWS * 3 * CCH];
__device__ __half g_att[(size_t)MROWS * CCH];
__device__ __half g_xh[(size_t)MROWS * CCH];
__device__ __half g_wqkv[(size_t)CCH * 3 * CCH];
__device__ __half g_wproj[(size_t)CCH * CCH];

// ---------------------------------------------------------------------------
// Helpers
// ---------------------------------------------------------------------------
__device__ __forceinline__ uint32_t sptr(const void* p) {
    return (uint32_t)__cvta_generic_to_shared(p);
}
__device__ __forceinline__ void cpa16(uint32_t d, const void* s) {
    asm volatile("cp.async.ca.shared.global [%0], [%1], 16;" :: "r"(d), "l"(s));
}
#define CP_COMMIT() asm volatile("cp.async.commit_group;" ::)
#define CP_WAIT(N)  asm volatile("cp.async.wait_group %0;" :: "n"(N))

__device__ __forceinline__ void ldsm4(uint32_t& r0, uint32_t& r1, uint32_t& r2,
                                      uint32_t& r3, uint32_t addr) {
    asm volatile("ldmatrix.sync.aligned.m8n8.x4.shared.b16 {%0,%1,%2,%3}, [%4];"
                 : "=r"(r0), "=r"(r1), "=r"(r2), "=r"(r3) : "r"(addr));
}
__device__ __forceinline__ void ldsm4t(uint32_t& r0, uint32_t& r1, uint32_t& r2,
                                       uint32_t& r3, uint32_t addr) {
    asm volatile("ldmatrix.sync.aligned.m8n8.x4.trans.shared.b16 {%0,%1,%2,%3}, [%4];"
                 : "=r"(r0), "=r"(r1), "=r"(r2), "=r"(r3) : "r"(addr));
}
__device__ __forceinline__ void mma16816(float c[4], const uint32_t a[4],
                                         uint32_t b0, uint32_t b1) {
    asm volatile(
        "mma.sync.aligned.m16n8k16.row.col.f32.f16.f16.f32 "
        "{%0,%1,%2,%3}, {%4,%5,%6,%7}, {%8,%9}, {%0,%1,%2,%3};\n"
        : "+f"(c[0]), "+f"(c[1]), "+f"(c[2]), "+f"(c[3])
        : "r"(a[0]), "r"(a[1]), "r"(a[2]), "r"(a[3]), "r"(b0), "r"(b1));
}
__device__ __forceinline__ uint32_t h2u(__half2 h) { return *reinterpret_cast<uint32_t*>(&h); }
__device__ __forceinline__ uint32_t ex2_f16x2(uint32_t v) {
    uint32_t r;
    asm("ex2.approx.f16x2 %0, %1;" : "=r"(r) : "r"(v));
    return r;
}

// ---------------------------------------------------------------------------
// fp32 -> fp16 conversion pre-pass (single fused launch for x, Wqkv, Wproj)
// ---------------------------------------------------------------------------
__global__ void cvt_f2h3(const float* __restrict__ s0, __half* __restrict__ d0, int n0,
                         const float* __restrict__ s1, __half* __restrict__ d1, int n1,
                         const float* __restrict__ s2, __half* __restrict__ d2, int n2) {
    int i = blockIdx.x * blockDim.x + threadIdx.x;
    const float* src; __half* dst;
    if (i < n0) { src = s0; dst = d0; }
    else if (i < n0 + n1) { src = s1; dst = d1; i -= n0; }
    else if (i < n0 + n1 + n2) { src = s2; dst = d2; i -= n0 + n1; }
    else return;
    float4 v = reinterpret_cast<const float4*>(src)[i];
    __half2* d = reinterpret_cast<__half2*>(dst) + 2 * i;
    d[0] = __floats2half2_rn(v.x, v.y);
    d[1] = __floats2half2_rn(v.z, v.w);
}

// ---------------------------------------------------------------------------
// FP16 GEMM + fp32 bias.  Block 128(M) x 128(N), 256 thr (8 warps, 64x32 warp
// tiles), BK=32, 2-stage cp.async, 2 blocks/SM.   (the proven 215.1 config)
// ---------------------------------------------------------------------------
#define GAS 40
#define GBS 136
#define GA_TILE (128 * GAS)
#define GB_TILE (32 * GBS)
#define GEMM_SMEM ((2 * GA_TILE + 2 * GB_TILE) * 2)

__global__ __launch_bounds__(256, 2)
void gemm_f16(const __half* __restrict__ A, const __half* __restrict__ B,
              const float* __restrict__ bias, __half* __restrict__ Ch,
              float* __restrict__ Cf, int M, int N, int K) {
    extern __shared__ __half sm[];
    __half* AsB = sm;                  // [2][128][GAS]
    __half* BsB = sm + 2 * GA_TILE;    // [2][32][GBS]

    const int tid = threadIdx.x;
    const int w = tid >> 5, lane = tid & 31;
    const int g = lane >> 2, tg = lane & 3;
    const int wm = (w & 1) * 64, wn = (w >> 1) * 32;
    const int rowBase = blockIdx.y * 128;
    const int colBase = blockIdx.x * 128;

    int aRow[2], aC8[2], bRow[2], bC8[2];
#pragma unroll
    for (int i = 0; i < 2; i++) {
        int idx = i * 256 + tid;
        aRow[i] = idx >> 2; aC8[i] = (idx & 3) * 8;
        bRow[i] = idx >> 4; bC8[i] = (idx & 15) * 8;
    }

    const int aLrow = lane & 15, aLk = (lane >> 4) * 8;
    const int bLk = ((lane >> 3) & 1) * 8 + (lane & 7), bLn = (lane >> 4) * 8;

    auto issue = [&](int stage, int k0) {
        __half* as = AsB + stage * GA_TILE;
        __half* bs = BsB + stage * GB_TILE;
#pragma unroll
        for (int i = 0; i < 2; i++) {
            cpa16(sptr(&as[aRow[i] * GAS + aC8[i]]),
                  &A[(size_t)(rowBase + aRow[i]) * K + k0 + aC8[i]]);
            cpa16(sptr(&bs[bRow[i] * GBS + bC8[i]]),
                  &B[(size_t)(k0 + bRow[i]) * N + colBase + bC8[i]]);
        }
        CP_COMMIT();
    };

    issue(0, 0);

    float acc[4][4][4];
#pragma unroll
    for (int mt = 0; mt < 4; mt++)
#pragma unroll
        for (int nt = 0; nt < 4; nt++)
#pragma unroll
            for (int r = 0; r < 4; r++) acc[mt][nt][r] = 0.f;

    const int KT = K >> 5;
    for (int t = 0; t < KT; t++) {
        const int cur = t & 1;
        if (t + 1 < KT) { issue(cur ^ 1, (t + 1) * 32); CP_WAIT(1); }
        else            { CP_WAIT(0); }
        __syncthreads();

        const __half* as = AsB + cur * GA_TILE;
        const __half* bs = BsB + cur * GB_TILE;
#pragma unroll
        for (int s = 0; s < 2; s++) {
            const int k16 = s * 16;
            uint32_t a[4][4];
#pragma unroll
            for (int mt = 0; mt < 4; mt++)
                ldsm4(a[mt][0], a[mt][1], a[mt][2], a[mt][3],
                      sptr(&as[(wm + mt * 16 + aLrow) * GAS + k16 + aLk]));
#pragma unroll
            for (int ntp = 0; ntp < 2; ntp++) {
                uint32_t b0e, b1e, b0o, b1o;
                ldsm4t(b0e, b1e, b0o, b1o,
                       sptr(&bs[(k16 + bLk) * GBS + wn + ntp * 16 + bLn]));
#pragma unroll
                for (int mt = 0; mt < 4; mt++) {
                    mma16816(acc[mt][2 * ntp], a[mt], b0e, b1e);
                    mma16816(acc[mt][2 * ntp + 1], a[mt], b0o, b1o);
                }
            }
        }
        __syncthreads();
    }

    // epilogue
#pragma unroll
    for (int mt = 0; mt < 4; mt++) {
        const int r0 = rowBase + wm + mt * 16 + g;
#pragma unroll
        for (int nt = 0; nt < 4; nt++) {
            const int col = colBase + wn + nt * 8 + tg * 2;
            const float bx = bias[col], by = bias[col + 1];
            float v00 = acc[mt][nt][0] + bx, v01 = acc[mt][nt][1] + by;
            float v10 = acc[mt][nt][2] + bx, v11 = acc[mt][nt][3] + by;
            if (Cf) {
                float2 o0 = {v00, v01}, o1 = {v10, v11};
                *reinterpret_cast<float2*>(&Cf[(size_t)r0 * N + col]) = o0;
                *reinterpret_cast<float2*>(&Cf[(size_t)(r0 + 8) * N + col]) = o1;
            } else {
                *reinterpret_cast<__half2*>(&Ch[(size_t)r0 * N + col]) =
                    __floats2half2_rn(v00, v01);
                *reinterpret_cast<__half2*>(&Ch[(size_t)(r0 + 8) * N + col]) =
                    __floats2half2_rn(v10, v11);
            }
        }
    }
}

// ---------------------------------------------------------------------------
// Small-tile FP16 GEMM for the proj stage: 64(M) x 128(N) CTA, 256 thr
// (8 warps, 32x32 warp tiles), BK=32, 2-stage cp.async, 3 blocks/SM.
// fp32 output + bias.
// ---------------------------------------------------------------------------
#define SA_TILE (64 * GAS)
#define SGEMM_SMEM ((2 * SA_TILE + 2 * GB_TILE) * 2)

__global__ __launch_bounds__(256, 3)
void gemm_f16_s64(const __half* __restrict__ A, const __half* __restrict__ B,
                  const float* __restrict__ bias, float* __restrict__ Cf,
                  int M, int N, int K) {
    extern __shared__ __half sm[];
    __half* AsB = sm;                  // [2][64][GAS]
    __half* BsB = sm + 2 * SA_TILE;    // [2][32][GBS]

    const int tid = threadIdx.x;
    const int w = tid >> 5, lane = tid & 31;
    const int g = lane >> 2, tg = lane & 3;
    const int wm = (w & 1) * 32, wn = (w >> 1) * 32;
    const int rowBase = blockIdx.y * 64;
    const int colBase = blockIdx.x * 128;

    // A: 64x32h = 256 chunks (1/thr); B: 32x128h = 512 chunks (2/thr)
    const int aRow = tid >> 2, aC8 = (tid & 3) * 8;
    int bRow[2], bC8[2];
#pragma unroll
    for (int i = 0; i < 2; i++) {
        int idx = i * 256 + tid;
        bRow[i] = idx >> 4; bC8[i] = (idx & 15) * 8;
    }

    const int aLrow = lane & 15, aLk = (lane >> 4) * 8;
    const int bLk = ((lane >> 3) & 1) * 8 + (lane & 7), bLn = (lane >> 4) * 8;

    auto issue = [&](int stage, int k0) {
        __half* as = AsB + stage * SA_TILE;
        __half* bs = BsB + stage * GB_TILE;
        cpa16(sptr(&as[aRow * GAS + aC8]),
              &A[(size_t)(rowBase + aRow) * K + k0 + aC8]);
#pragma unroll
        for (int i = 0; i < 2; i++)
            cpa16(sptr(&bs[bRow[i] * GBS + bC8[i]]),
                  &B[(size_t)(k0 + bRow[i]) * N + colBase + bC8[i]]);
        CP_COMMIT();
    };

    issue(0, 0);

    float acc[2][4][4];
#pragma unroll
    for (int mt = 0; mt < 2; mt++)
#pragma unroll
        for (int nt = 0; nt < 4; nt++)
#pragma unroll
            for (int r = 0; r < 4; r++) acc[mt][nt][r] = 0.f;

    const int KT = K >> 5;
    for (int t = 0; t < KT; t++) {
        const int cur = t & 1;
        if (t + 1 < KT) { issue(cur ^ 1, (t + 1) * 32); CP_WAIT(1); }
        else            { CP_WAIT(0); }
        __syncthreads();

        const __half* as = AsB + cur * SA_TILE;
        const __half* bs = BsB + cur * GB_TILE;
#pragma unroll
        for (int s = 0; s < 2; s++) {
            const int k16 = s * 16;
            uint32_t a[2][4];
#pragma unroll
            for (int mt = 0; mt < 2; mt++)
                ldsm4(a[mt][0], a[mt][1], a[mt][2], a[mt][3],
                      sptr(&as[(wm + mt * 16 + aLrow) * GAS + k16 + aLk]));
#pragma unroll
            for (int ntp = 0; ntp < 2; ntp++) {
                uint32_t b0e, b1e, b0o, b1o;
                ldsm4t(b0e, b1e, b0o, b1o,
                       sptr(&bs[(k16 + bLk) * GBS + wn + ntp * 16 + bLn]));
#pragma unroll
                for (int mt = 0; mt < 2; mt++) {
                    mma16816(acc[mt][2 * ntp], a[mt], b0e, b1e);
                    mma16816(acc[mt][2 * ntp + 1], a[mt], b0o, b1o);
                }
            }
        }
        __syncthreads();
    }

    // epilogue (fp32 + bias)
#pragma unroll
    for (int mt = 0; mt < 2; mt++) {
        const int r0 = rowBase + wm + mt * 16 + g;
#pragma unroll
        for (int nt = 0; nt < 4; nt++) {
            const int col = colBase + wn + nt * 8 + tg * 2;
            const float bx = bias[col], by = bias[col + 1];
            float2 o0 = {acc[mt][nt][0] + bx, acc[mt][nt][1] + by};
            float2 o1 = {acc[mt][nt][2] + bx, acc[mt][nt][3] + by};
            *reinterpret_cast<float2*>(&Cf[(size_t)r0 * N + col]) = o0;
            *reinterpret_cast<float2*>(&Cf[(size_t)(r0 + 8) * N + col]) = o1;
        }
    }
}

// ---------------------------------------------------------------------------
// FP16 flash attention (causal).  256 thr (8 warps), BQ=128 (16 rows/warp),
// BKV=64, 3-stage cp.async KV ring, 2 blocks/SM.  log2-domain scores,
// f16x2 exp2 softmax, vote-skipped O rescale.   (the proven 215.1 config)
// ---------------------------------------------------------------------------
#define AS 72   // smem row stride in halves (144B)
#define KV_TILE (64 * AS)
#define ATT_SMEM ((128 * AS + 3 * 2 * KV_TILE) * 2)

__global__ __launch_bounds__(256, 2)
void attn_f16(const __half* __restrict__ qkv, __half* __restrict__ out) {
    extern __shared__ __half smh[];
    __half* Qs = smh;                        // [128][AS]
    __half* KVs = smh + 128 * AS;            // [3][2][64][AS]

    const int qb = (gridDim.x - 1) - blockIdx.x;
    const int h = blockIdx.y, b = blockIdx.z;
    const int tid = threadIdx.x;
    const int w = tid >> 5, lane = tid & 31;
    const int g = lane >> 2, tg = lane & 3;

    const int aLrow = lane & 15, aLk = (lane >> 4) * 8;                        // Q
    const int kLn = ((lane >> 4) << 3) + (lane & 7), kLk = ((lane >> 3) & 1) * 8;  // K
    const int vLk = ((lane >> 3) & 1) * 8 + (lane & 7), vLn = (lane >> 4) * 8;     // V

    int kvRow[2], kvC8[2];
#pragma unroll
    for (int i = 0; i < 2; i++) {
        int idx = i * 256 + tid;
        kvRow[i] = idx >> 3; kvC8[i] = (idx & 7) * 8;
    }

    auto issueKV = [&](int stage, int kt) {
        __half* Ks = KVs + stage * 2 * KV_TILE;
        __half* Vs = Ks + KV_TILE;
#pragma unroll
        for (int i = 0; i < 2; i++) {
            const size_t gofs =
                ((size_t)(b * TT + kt * 64 + kvRow[i])) * (3 * CCH) + h * DD + kvC8[i];
            cpa16(sptr(&Ks[kvRow[i] * AS + kvC8[i]]), &qkv[gofs + CCH]);
            cpa16(sptr(&Vs[kvRow[i] * AS + kvC8[i]]), &qkv[gofs + 2 * CCH]);
        }
        CP_COMMIT();
    };

    const int ktmax = 2 * qb + 1;
    issueKV(0, 0);
    issueKV(1, 1);

#pragma unroll
    for (int i = 0; i < 4; i++) {
        const int idx = i * 256 + tid;
        const int row = idx >> 3, c8 = (idx & 7) * 8;
        const size_t gofs = ((size_t)(b * TT + qb * 128 + row)) * (3 * CCH) + h * DD + c8;
        *reinterpret_cast<uint4*>(&Qs[row * AS + c8]) =
            *reinterpret_cast<const uint4*>(&qkv[gofs]);
    }
    __syncthreads();

    // Q fragments; scale = 1/8 * log2(e)
    uint32_t qf[4][4];
    {
        const __half2 sc = __float2half2_rn(0.125f * 1.44269504f);
#pragma unroll
        for (int s = 0; s < 4; s++) {
            uint32_t r0, r1, r2, r3;
            ldsm4(r0, r1, r2, r3, sptr(&Qs[(w * 16 + aLrow) * AS + s * 16 + aLk]));
            qf[s][0] = h2u(__hmul2(*reinterpret_cast<__half2*>(&r0), sc));
            qf[s][1] = h2u(__hmul2(*reinterpret_cast<__half2*>(&r1), sc));
            qf[s][2] = h2u(__hmul2(*reinterpret_cast<__half2*>(&r2), sc));
            qf[s][3] = h2u(__hmul2(*reinterpret_cast<__half2*>(&r3), sc));
        }
    }

    float O[8][4];
#pragma unroll
    for (int nt = 0; nt < 8; nt++)
#pragma unroll
        for (int r = 0; r < 4; r++) O[nt][r] = 0.f;
    float mx0 = NEG_BIG, mx1 = NEG_BIG, l0 = 0.f, l1 = 0.f;

    const int qmin = qb * 128 + w * 16;

    int stage = 0;
    for (int kt = 0; kt <= ktmax; kt++) {
        if (kt + 2 <= ktmax) CP_WAIT(1); else CP_WAIT(0);
        __syncthreads();
        if (kt + 2 <= ktmax) {
            int ns = stage + 2; if (ns >= 3) ns -= 3;
            issueKV(ns, kt + 2);
        }

        const __half* Ks = KVs + stage * 2 * KV_TILE;
        const __half* Vs = Ks + KV_TILE;

        int rem = ((qmin + 15 - kt * 64) >> 3) + 1;
        const int ntc = rem < 8 ? rem : 8;
        if (ntc > 0) {
            const bool needmask = (kt * 64 + 63 > qmin);

            float s[8][4];
#pragma unroll
            for (int nt = 0; nt < 8; nt++)
#pragma unroll
                for (int r = 0; r < 4; r++) s[nt][r] = 0.f;

#pragma unroll
            for (int ks = 0; ks < 4; ks++) {
#pragma unroll
                for (int ntp = 0; ntp < 4; ntp++) {
                    if (2 * ntp < ntc) {
                        uint32_t b0e, b1e, b0o, b1o;
                        ldsm4(b0e, b1e, b0o, b1o,
                              sptr(&Ks[(ntp * 16 + kLn) * AS + ks * 16 + kLk]));
                        mma16816(s[2 * ntp], qf[ks], b0e, b1e);
                        mma16816(s[2 * ntp + 1], qf[ks], b0o, b1o);
                    }
                }
            }

            if (needmask) {
                const int r0 = qmin + g, r1 = r0 + 8;
#pragma unroll
                for (int nt = 0; nt < 8; nt++) {
                    if (nt < ntc) {
                        const int c0 = kt * 64 + nt * 8 + tg * 2, c1 = c0 + 1;
                        if (c0 > r0) s[nt][0] = NEG_BIG;
                        if (c1 > r0) s[nt][1] = NEG_BIG;
                        if (c0 > r1) s[nt][2] = NEG_BIG;
                        if (c1 > r1) s[nt][3] = NEG_BIG;
                    }
                }
            }

            float mt0 = NEG_BIG, mt1 = NEG_BIG;
#pragma unroll
            for (int nt = 0; nt < 8; nt++) {
                if (nt < ntc) {
                    mt0 = fmaxf(mt0, fmaxf(s[nt][0], s[nt][1]));
                    mt1 = fmaxf(mt1, fmaxf(s[nt][2], s[nt][3]));
                }
            }
            mt0 = fmaxf(mt0, __shfl_xor_sync(0xffffffffu, mt0, 1));
            mt0 = fmaxf(mt0, __shfl_xor_sync(0xffffffffu, mt0, 2));
            mt1 = fmaxf(mt1, __shfl_xor_sync(0xffffffffu, mt1, 1));
            mt1 = fmaxf(mt1, __shfl_xor_sync(0xffffffffu, mt1, 2));
            const float nm0 = fmaxf(mx0, mt0), nm1 = fmaxf(mx1, mt1);
            const bool upd = (nm0 > mx0) || (nm1 > mx1);
            const float c0 = exp2f(mx0 - nm0), c1 = exp2f(mx1 - nm1);

            uint32_t P0[8], P1[8];
            const __half2 nmh0 = __float2half2_rn(nm0);
            const __half2 nmh1 = __float2half2_rn(nm1);
            float rs0 = 0.f, rs1 = 0.f;
#pragma unroll
            for (int nt = 0; nt < 8; nt++) {
                if (nt < ntc) {
                    __half2 a0 = __hsub2(__floats2half2_rn(s[nt][0], s[nt][1]), nmh0);
                    __half2 a1 = __hsub2(__floats2half2_rn(s[nt][2], s[nt][3]), nmh1);
                    uint32_t p0 = ex2_f16x2(h2u(a0));
                    uint32_t p1 = ex2_f16x2(h2u(a1));
                    P0[nt] = p0; P1[nt] = p1;
                    float2 f0 = __half22float2(*reinterpret_cast<__half2*>(&p0));
                    float2 f1 = __half22float2(*reinterpret_cast<__half2*>(&p1));
                    rs0 += f0.x + f0.y;
                    rs1 += f1.x + f1.y;
                } else {
                    P0[nt] = 0u; P1[nt] = 0u;
                }
            }
            rs0 += __shfl_xor_sync(0xffffffffu, rs0, 1);
            rs0 += __shfl_xor_sync(0xffffffffu, rs0, 2);
            rs1 += __shfl_xor_sync(0xffffffffu, rs1, 1);
            rs1 += __shfl_xor_sync(0xffffffffu, rs1, 2);
            l0 = l0 * c0 + rs0;
            l1 = l1 * c1 + rs1;
            mx0 = nm0; mx1 = nm1;

            if (__any_sync(0xffffffffu, upd)) {
#pragma unroll
                for (int nt = 0; nt < 8; nt++) {
                    O[nt][0] *= c0; O[nt][1] *= c0;
                    O[nt][2] *= c1; O[nt][3] *= c1;
                }
            }

            const int spc = (ntc + 1) >> 1;
#pragma unroll
            for (int sp = 0; sp < 4; sp++) {
                if (sp < spc) {
                    uint32_t pa[4];
                    pa[0] = P0[2 * sp];
                    pa[1] = P1[2 * sp];
                    pa[2] = P0[2 * sp + 1];
                    pa[3] = P1[2 * sp + 1];
#pragma unroll
                    for (int ntp = 0; ntp < 4; ntp++) {
                        uint32_t b0e, b1e, b0o, b1o;
                        ldsm4t(b0e, b1e, b0o, b1o,
                               sptr(&Vs[(sp * 16 + vLk) * AS + ntp * 16 + vLn]));
                        mma16816(O[2 * ntp], pa, b0e, b1e);
                        mma16816(O[2 * ntp + 1], pa, b0o, b1o);
                    }
                }
            }
        }
        if (++stage == 3) stage = 0;
    }

    const float inv0 = 1.f / l0, inv1 = 1.f / l1;
    const int row0 = qb * 128 + w * 16 + g;
#pragma unroll
    for (int nt = 0; nt < 8; nt++) {
        const int col = h * DD + nt * 8 + tg * 2;
        *reinterpret_cast<__half2*>(&out[(size_t)(b * TT + row0) * CCH + col]) =
            __floats2half2_rn(O[nt][0] * inv0, O[nt][1] * inv0);
        *reinterpret_cast<__half2*>(&out[(size_t)(b * TT + row0 + 8) * CCH + col]) =
            __floats2half2_rn(O[nt][2] * inv1, O[nt][3] * inv1);
    }
}

// ---------------------------------------------------------------------------
extern "C" void kernel_launch(void* const* d_in, const int* in_sizes, int n_in,
                              void* d_out, int out_size) {
    const float* x     = (const float*)d_in[0];
    const float* Wqkv  = (const float*)d_in[1];
    const float* bqkv  = (const float*)d_in[2];
    const float* Wproj = (const float*)d_in[3];
    const float* bproj = (const float*)d_in[4];
    float* out = (float*)d_out;

    __half *qkv, *att, *xh, *wqkv, *wproj;
    cudaGetSymbolAddress((void**)&qkv, g_qkv);
    cudaGetSymbolAddress((void**)&att, g_att);
    cudaGetSymbolAddress((void**)&xh, g_xh);
    cudaGetSymbolAddress((void**)&wqkv, g_wqkv);
    cudaGetSymbolAddress((void**)&wproj, g_wproj);

    // 0) fused fp32 -> fp16 pre-pass
    {
        int n4x = MROWS * CCH / 4;
        int n4q = CCH * 3 * CCH / 4;
        int n4p = CCH * CCH / 4;
        int total = n4x + n4q + n4p;
        cvt_f2h3<<<(total + 255) / 256, 256>>>(x, xh, n4x, Wqkv, wqkv, n4q,
                                               Wproj, wproj, n4p);
    }
    // 1) QKV projection -> half  (128x128 tiles, 2 blocks/SM)
    {
        cudaFuncSetAttribute(gemm_f16, cudaFuncAttributeMaxDynamicSharedMemorySize,
                             GEMM_SMEM);
        dim3 grid(3 * CCH / 128, MROWS / 128);
        gemm_f16<<<grid, 256, GEMM_SMEM>>>(xh, wqkv, bqkv, qkv, nullptr,
                                           MROWS, 3 * CCH, CCH);
    }
    // 2) Flash attention -> half
    {
        cudaFuncSetAttribute(attn_f16, cudaFuncAttributeMaxDynamicSharedMemorySize,
                             ATT_SMEM);
        dim3 grid(TT / 128, HH, BB);
        attn_f16<<<grid, 256, ATT_SMEM>>>(qkv, att);
    }
    // 3) Output projection -> fp32  (64x128 tiles, 3 blocks/SM)
    {
        cudaFuncSetAttribute(gemm_f16_s64, cudaFuncAttributeMaxDynamicSharedMemorySize,
                             SGEMM_SMEM);
        dim3 grid(CCH / 128, MROWS / 64);
        gemm_f16_s64<<<grid, 256, SGEMM_SMEM>>>(att, wproj, bproj, out,
                                                MROWS, CCH, CCH);
    }
}

// round 17
// speedup vs baseline: 1.5521x; 1.0506x over previous
#include <cuda_runtime.h>
#include <cuda_fp16.h>
#include <cstdint>

#define BB 2
#define TT 2048
#define CCH 1024
#define HH 16
#define DD 64
#define MROWS (BB * TT)       // 4096
#define NEG_BIG (-1e30f)

// Scratch (half-precision working set)
__device__ __half g_qkv[(size_t)MROWS * 3 * CCH];
__device__ __half g_att[(size_t)MROWS * CCH];
__device__ __half g_xh[(size_t)MROWS * CCH];
__device__ __half g_wqkv[(size_t)CCH * 3 * CCH];
__device__ __half g_wproj[(size_t)CCH * CCH];

// ---------------------------------------------------------------------------
// Helpers
// ---------------------------------------------------------------------------
__device__ __forceinline__ uint32_t sptr(const void* p) {
    return (uint32_t)__cvta_generic_to_shared(p);
}
__device__ __forceinline__ void cpa16(uint32_t d, const void* s) {
    asm volatile("cp.async.ca.shared.global [%0], [%1], 16;" :: "r"(d), "l"(s));
}
#define CP_COMMIT() asm volatile("cp.async.commit_group;" ::)
#define CP_WAIT(N)  asm volatile("cp.async.wait_group %0;" :: "n"(N))

__device__ __forceinline__ void ldsm4(uint32_t& r0, uint32_t& r1, uint32_t& r2,
                                      uint32_t& r3, uint32_t addr) {
    asm volatile("ldmatrix.sync.aligned.m8n8.x4.shared.b16 {%0,%1,%2,%3}, [%4];"
                 : "=r"(r0), "=r"(r1), "=r"(r2), "=r"(r3) : "r"(addr));
}
__device__ __forceinline__ void ldsm4t(uint32_t& r0, uint32_t& r1, uint32_t& r2,
                                       uint32_t& r3, uint32_t addr) {
    asm volatile("ldmatrix.sync.aligned.m8n8.x4.trans.shared.b16 {%0,%1,%2,%3}, [%4];"
                 : "=r"(r0), "=r"(r1), "=r"(r2), "=r"(r3) : "r"(addr));
}
__device__ __forceinline__ void mma16816(float c[4], const uint32_t a[4],
                                         uint32_t b0, uint32_t b1) {
    asm volatile(
        "mma.sync.aligned.m16n8k16.row.col.f32.f16.f16.f32 "
        "{%0,%1,%2,%3}, {%4,%5,%6,%7}, {%8,%9}, {%0,%1,%2,%3};\n"
        : "+f"(c[0]), "+f"(c[1]), "+f"(c[2]), "+f"(c[3])
        : "r"(a[0]), "r"(a[1]), "r"(a[2]), "r"(a[3]), "r"(b0), "r"(b1));
}
__device__ __forceinline__ uint32_t h2u(__half2 h) { return *reinterpret_cast<uint32_t*>(&h); }
__device__ __forceinline__ uint32_t ex2_f16x2(uint32_t v) {
    uint32_t r;
    asm("ex2.approx.f16x2 %0, %1;" : "=r"(r) : "r"(v));
    return r;
}

// ---------------------------------------------------------------------------
// fp32 -> fp16 conversion pre-pass (single fused launch for x, Wqkv, Wproj)
// ---------------------------------------------------------------------------
__global__ void cvt_f2h3(const float* __restrict__ s0, __half* __restrict__ d0, int n0,
                         const float* __restrict__ s1, __half* __restrict__ d1, int n1,
                         const float* __restrict__ s2, __half* __restrict__ d2, int n2) {
    int i = blockIdx.x * blockDim.x + threadIdx.x;
    const float* src; __half* dst;
    if (i < n0) { src = s0; dst = d0; }
    else if (i < n0 + n1) { src = s1; dst = d1; i -= n0; }
    else if (i < n0 + n1 + n2) { src = s2; dst = d2; i -= n0 + n1; }
    else return;
    float4 v = reinterpret_cast<const float4*>(src)[i];
    __half2* d = reinterpret_cast<__half2*>(dst) + 2 * i;
    d[0] = __floats2half2_rn(v.x, v.y);
    d[1] = __floats2half2_rn(v.z, v.w);
}

// ---------------------------------------------------------------------------
// FP16 GEMM + fp32 bias.  Block 128(M) x 128(N), 256 thr (8 warps, 64x32 warp
// tiles), BK=32, 2-stage cp.async, 2 blocks/SM.   (the proven 215.1 config)
// ---------------------------------------------------------------------------
#define GAS 40
#define GBS 136
#define GA_TILE (128 * GAS)
#define GB_TILE (32 * GBS)
#define GEMM_SMEM ((2 * GA_TILE + 2 * GB_TILE) * 2)

__global__ __launch_bounds__(256, 2)
void gemm_f16(const __half* __restrict__ A, const __half* __restrict__ B,
              const float* __restrict__ bias, __half* __restrict__ Ch,
              float* __restrict__ Cf, int M, int N, int K) {
    extern __shared__ __half sm[];
    __half* AsB = sm;                  // [2][128][GAS]
    __half* BsB = sm + 2 * GA_TILE;    // [2][32][GBS]

    const int tid = threadIdx.x;
    const int w = tid >> 5, lane = tid & 31;
    const int g = lane >> 2, tg = lane & 3;
    const int wm = (w & 1) * 64, wn = (w >> 1) * 32;
    const int rowBase = blockIdx.y * 128;
    const int colBase = blockIdx.x * 128;

    int aRow[2], aC8[2], bRow[2], bC8[2];
#pragma unroll
    for (int i = 0; i < 2; i++) {
        int idx = i * 256 + tid;
        aRow[i] = idx >> 2; aC8[i] = (idx & 3) * 8;
        bRow[i] = idx >> 4; bC8[i] = (idx & 15) * 8;
    }

    const int aLrow = lane & 15, aLk = (lane >> 4) * 8;
    const int bLk = ((lane >> 3) & 1) * 8 + (lane & 7), bLn = (lane >> 4) * 8;

    auto issue = [&](int stage, int k0) {
        __half* as = AsB + stage * GA_TILE;
        __half* bs = BsB + stage * GB_TILE;
#pragma unroll
        for (int i = 0; i < 2; i++) {
            cpa16(sptr(&as[aRow[i] * GAS + aC8[i]]),
                  &A[(size_t)(rowBase + aRow[i]) * K + k0 + aC8[i]]);
            cpa16(sptr(&bs[bRow[i] * GBS + bC8[i]]),
                  &B[(size_t)(k0 + bRow[i]) * N + colBase + bC8[i]]);
        }
        CP_COMMIT();
    };

    issue(0, 0);

    float acc[4][4][4];
#pragma unroll
    for (int mt = 0; mt < 4; mt++)
#pragma unroll
        for (int nt = 0; nt < 4; nt++)
#pragma unroll
            for (int r = 0; r < 4; r++) acc[mt][nt][r] = 0.f;

    const int KT = K >> 5;
    for (int t = 0; t < KT; t++) {
        const int cur = t & 1;
        if (t + 1 < KT) { issue(cur ^ 1, (t + 1) * 32); CP_WAIT(1); }
        else            { CP_WAIT(0); }
        __syncthreads();

        const __half* as = AsB + cur * GA_TILE;
        const __half* bs = BsB + cur * GB_TILE;
#pragma unroll
        for (int s = 0; s < 2; s++) {
            const int k16 = s * 16;
            uint32_t a[4][4];
#pragma unroll
            for (int mt = 0; mt < 4; mt++)
                ldsm4(a[mt][0], a[mt][1], a[mt][2], a[mt][3],
                      sptr(&as[(wm + mt * 16 + aLrow) * GAS + k16 + aLk]));
#pragma unroll
            for (int ntp = 0; ntp < 2; ntp++) {
                uint32_t b0e, b1e, b0o, b1o;
                ldsm4t(b0e, b1e, b0o, b1o,
                       sptr(&bs[(k16 + bLk) * GBS + wn + ntp * 16 + bLn]));
#pragma unroll
                for (int mt = 0; mt < 4; mt++) {
                    mma16816(acc[mt][2 * ntp], a[mt], b0e, b1e);
                    mma16816(acc[mt][2 * ntp + 1], a[mt], b0o, b1o);
                }
            }
        }
        __syncthreads();
    }

    // epilogue
#pragma unroll
    for (int mt = 0; mt < 4; mt++) {
        const int r0 = rowBase + wm + mt * 16 + g;
#pragma unroll
        for (int nt = 0; nt < 4; nt++) {
            const int col = colBase + wn + nt * 8 + tg * 2;
            const float bx = bias[col], by = bias[col + 1];
            float v00 = acc[mt][nt][0] + bx, v01 = acc[mt][nt][1] + by;
            float v10 = acc[mt][nt][2] + bx, v11 = acc[mt][nt][3] + by;
            if (Cf) {
                float2 o0 = {v00, v01}, o1 = {v10, v11};
                *reinterpret_cast<float2*>(&Cf[(size_t)r0 * N + col]) = o0;
                *reinterpret_cast<float2*>(&Cf[(size_t)(r0 + 8) * N + col]) = o1;
            } else {
                *reinterpret_cast<__half2*>(&Ch[(size_t)r0 * N + col]) =
                    __floats2half2_rn(v00, v01);
                *reinterpret_cast<__half2*>(&Ch[(size_t)(r0 + 8) * N + col]) =
                    __floats2half2_rn(v10, v11);
            }
        }
    }
}

// ---------------------------------------------------------------------------
// FP16 flash attention (causal).  256 thr (8 warps), BQ=128 (16 rows/warp),
// BKV=64, 3-stage cp.async KV ring, 2 blocks/SM.  log2-domain scores, f16x2
// exp2 softmax, vote-skipped O rescale.  NEW: cp.async Q load + full-tile /
// boundary-tile specialization (no predicates or masking on interior tiles).
// ---------------------------------------------------------------------------
#define AS 72   // smem row stride in halves (144B)
#define KV_TILE (64 * AS)
#define ATT_SMEM ((128 * AS + 3 * 2 * KV_TILE) * 2)

__global__ __launch_bounds__(256, 2)
void attn_f16(const __half* __restrict__ qkv, __half* __restrict__ out) {
    extern __shared__ __half smh[];
    __half* Qs = smh;                        // [128][AS]
    __half* KVs = smh + 128 * AS;            // [3][2][64][AS]

    const int qb = (gridDim.x - 1) - blockIdx.x;
    const int h = blockIdx.y, b = blockIdx.z;
    const int tid = threadIdx.x;
    const int w = tid >> 5, lane = tid & 31;
    const int g = lane >> 2, tg = lane & 3;

    const int aLrow = lane & 15, aLk = (lane >> 4) * 8;                        // Q
    const int kLn = ((lane >> 4) << 3) + (lane & 7), kLk = ((lane >> 3) & 1) * 8;  // K
    const int vLk = ((lane >> 3) & 1) * 8 + (lane & 7), vLn = (lane >> 4) * 8;     // V

    int kvRow[2], kvC8[2];
#pragma unroll
    for (int i = 0; i < 2; i++) {
        int idx = i * 256 + tid;
        kvRow[i] = idx >> 3; kvC8[i] = (idx & 7) * 8;
    }

    auto issueKV = [&](int stage, int kt) {
        __half* Ks = KVs + stage * 2 * KV_TILE;
        __half* Vs = Ks + KV_TILE;
#pragma unroll
        for (int i = 0; i < 2; i++) {
            const size_t gofs =
                ((size_t)(b * TT + kt * 64 + kvRow[i])) * (3 * CCH) + h * DD + kvC8[i];
            cpa16(sptr(&Ks[kvRow[i] * AS + kvC8[i]]), &qkv[gofs + CCH]);
            cpa16(sptr(&Vs[kvRow[i] * AS + kvC8[i]]), &qkv[gofs + 2 * CCH]);
        }
        CP_COMMIT();
    };

    const int ktmax = 2 * qb + 1;
    // group0: KV0;  group1: Q;  group2: KV1
    issueKV(0, 0);
#pragma unroll
    for (int i = 0; i < 4; i++) {
        const int idx = i * 256 + tid;
        const int row = idx >> 3, c8 = (idx & 7) * 8;
        const size_t gofs = ((size_t)(b * TT + qb * 128 + row)) * (3 * CCH) + h * DD + c8;
        cpa16(sptr(&Qs[row * AS + c8]), &qkv[gofs]);
    }
    CP_COMMIT();
    issueKV(1, 1);

    CP_WAIT(1);          // KV0 + Q landed
    __syncthreads();

    // Q fragments; scale = 1/8 * log2(e)
    uint32_t qf[4][4];
    {
        const __half2 sc = __float2half2_rn(0.125f * 1.44269504f);
#pragma unroll
        for (int s = 0; s < 4; s++) {
            uint32_t r0, r1, r2, r3;
            ldsm4(r0, r1, r2, r3, sptr(&Qs[(w * 16 + aLrow) * AS + s * 16 + aLk]));
            qf[s][0] = h2u(__hmul2(*reinterpret_cast<__half2*>(&r0), sc));
            qf[s][1] = h2u(__hmul2(*reinterpret_cast<__half2*>(&r1), sc));
            qf[s][2] = h2u(__hmul2(*reinterpret_cast<__half2*>(&r2), sc));
            qf[s][3] = h2u(__hmul2(*reinterpret_cast<__half2*>(&r3), sc));
        }
    }

    float O[8][4];
#pragma unroll
    for (int nt = 0; nt < 8; nt++)
#pragma unroll
        for (int r = 0; r < 4; r++) O[nt][r] = 0.f;
    float mx0 = NEG_BIG, mx1 = NEG_BIG, l0 = 0.f, l1 = 0.f;

    const int qmin = qb * 128 + w * 16;

    int stage = 0;
    for (int kt = 0; kt <= ktmax; kt++) {
        if (kt + 2 <= ktmax) CP_WAIT(1); else CP_WAIT(0);
        __syncthreads();
        if (kt + 2 <= ktmax) {
            int ns = stage + 2; if (ns >= 3) ns -= 3;
            issueKV(ns, kt + 2);
        }

        const __half* Ks = KVs + stage * 2 * KV_TILE;
        const __half* Vs = Ks + KV_TILE;

        const bool full = (kt * 64 + 63 <= qmin);
        if (full) {
            // ---------- interior tile: no predicates, no masking ----------
            float s[8][4];
#pragma unroll
            for (int nt = 0; nt < 8; nt++)
#pragma unroll
                for (int r = 0; r < 4; r++) s[nt][r] = 0.f;

#pragma unroll
            for (int ks = 0; ks < 4; ks++) {
#pragma unroll
                for (int ntp = 0; ntp < 4; ntp++) {
                    uint32_t b0e, b1e, b0o, b1o;
                    ldsm4(b0e, b1e, b0o, b1o,
                          sptr(&Ks[(ntp * 16 + kLn) * AS + ks * 16 + kLk]));
                    mma16816(s[2 * ntp], qf[ks], b0e, b1e);
                    mma16816(s[2 * ntp + 1], qf[ks], b0o, b1o);
                }
            }

            float mt0 = NEG_BIG, mt1 = NEG_BIG;
#pragma unroll
            for (int nt = 0; nt < 8; nt++) {
                mt0 = fmaxf(mt0, fmaxf(s[nt][0], s[nt][1]));
                mt1 = fmaxf(mt1, fmaxf(s[nt][2], s[nt][3]));
            }
            mt0 = fmaxf(mt0, __shfl_xor_sync(0xffffffffu, mt0, 1));
            mt0 = fmaxf(mt0, __shfl_xor_sync(0xffffffffu, mt0, 2));
            mt1 = fmaxf(mt1, __shfl_xor_sync(0xffffffffu, mt1, 1));
            mt1 = fmaxf(mt1, __shfl_xor_sync(0xffffffffu, mt1, 2));
            const float nm0 = fmaxf(mx0, mt0), nm1 = fmaxf(mx1, mt1);
            const bool upd = (nm0 > mx0) || (nm1 > mx1);
            const float c0 = exp2f(mx0 - nm0), c1 = exp2f(mx1 - nm1);

            uint32_t P0[8], P1[8];
            const __half2 nmh0 = __float2half2_rn(nm0);
            const __half2 nmh1 = __float2half2_rn(nm1);
            float rs0 = 0.f, rs1 = 0.f;
#pragma unroll
            for (int nt = 0; nt < 8; nt++) {
                __half2 a0 = __hsub2(__floats2half2_rn(s[nt][0], s[nt][1]), nmh0);
                __half2 a1 = __hsub2(__floats2half2_rn(s[nt][2], s[nt][3]), nmh1);
                uint32_t p0 = ex2_f16x2(h2u(a0));
                uint32_t p1 = ex2_f16x2(h2u(a1));
                P0[nt] = p0; P1[nt] = p1;
                float2 f0 = __half22float2(*reinterpret_cast<__half2*>(&p0));
                float2 f1 = __half22float2(*reinterpret_cast<__half2*>(&p1));
                rs0 += f0.x + f0.y;
                rs1 += f1.x + f1.y;
            }
            rs0 += __shfl_xor_sync(0xffffffffu, rs0, 1);
            rs0 += __shfl_xor_sync(0xffffffffu, rs0, 2);
            rs1 += __shfl_xor_sync(0xffffffffu, rs1, 1);
            rs1 += __shfl_xor_sync(0xffffffffu, rs1, 2);
            l0 = l0 * c0 + rs0;
            l1 = l1 * c1 + rs1;
            mx0 = nm0; mx1 = nm1;

            if (__any_sync(0xffffffffu, upd)) {
#pragma unroll
                for (int nt = 0; nt < 8; nt++) {
                    O[nt][0] *= c0; O[nt][1] *= c0;
                    O[nt][2] *= c1; O[nt][3] *= c1;
                }
            }

#pragma unroll
            for (int sp = 0; sp < 4; sp++) {
                uint32_t pa[4];
                pa[0] = P0[2 * sp];
                pa[1] = P1[2 * sp];
                pa[2] = P0[2 * sp + 1];
                pa[3] = P1[2 * sp + 1];
#pragma unroll
                for (int ntp = 0; ntp < 4; ntp++) {
                    uint32_t b0e, b1e, b0o, b1o;
                    ldsm4t(b0e, b1e, b0o, b1o,
                           sptr(&Vs[(sp * 16 + vLk) * AS + ntp * 16 + vLn]));
                    mma16816(O[2 * ntp], pa, b0e, b1e);
                    mma16816(O[2 * ntp + 1], pa, b0o, b1o);
                }
            }
        } else {
            // ---------- boundary tile: predicated + masked ----------
            int rem = ((qmin + 15 - kt * 64) >> 3) + 1;
            const int ntc = rem < 8 ? rem : 8;
            if (ntc > 0) {
                float s[8][4];
#pragma unroll
                for (int nt = 0; nt < 8; nt++)
#pragma unroll
                    for (int r = 0; r < 4; r++) s[nt][r] = 0.f;

#pragma unroll
                for (int ks = 0; ks < 4; ks++) {
#pragma unroll
                    for (int ntp = 0; ntp < 4; ntp++) {
                        if (2 * ntp < ntc) {
                            uint32_t b0e, b1e, b0o, b1o;
                            ldsm4(b0e, b1e, b0o, b1o,
                                  sptr(&Ks[(ntp * 16 + kLn) * AS + ks * 16 + kLk]));
                            mma16816(s[2 * ntp], qf[ks], b0e, b1e);
                            mma16816(s[2 * ntp + 1], qf[ks], b0o, b1o);
                        }
                    }
                }

                {
                    const int r0 = qmin + g, r1 = r0 + 8;
#pragma unroll
                    for (int nt = 0; nt < 8; nt++) {
                        if (nt < ntc) {
                            const int c0 = kt * 64 + nt * 8 + tg * 2, c1 = c0 + 1;
                            if (c0 > r0) s[nt][0] = NEG_BIG;
                            if (c1 > r0) s[nt][1] = NEG_BIG;
                            if (c0 > r1) s[nt][2] = NEG_BIG;
                            if (c1 > r1) s[nt][3] = NEG_BIG;
                        }
                    }
                }

                float mt0 = NEG_BIG, mt1 = NEG_BIG;
#pragma unroll
                for (int nt = 0; nt < 8; nt++) {
                    if (nt < ntc) {
                        mt0 = fmaxf(mt0, fmaxf(s[nt][0], s[nt][1]));
                        mt1 = fmaxf(mt1, fmaxf(s[nt][2], s[nt][3]));
                    }
                }
                mt0 = fmaxf(mt0, __shfl_xor_sync(0xffffffffu, mt0, 1));
                mt0 = fmaxf(mt0, __shfl_xor_sync(0xffffffffu, mt0, 2));
                mt1 = fmaxf(mt1, __shfl_xor_sync(0xffffffffu, mt1, 1));
                mt1 = fmaxf(mt1, __shfl_xor_sync(0xffffffffu, mt1, 2));
                const float nm0 = fmaxf(mx0, mt0), nm1 = fmaxf(mx1, mt1);
                const bool upd = (nm0 > mx0) || (nm1 > mx1);
                const float c0 = exp2f(mx0 - nm0), c1 = exp2f(mx1 - nm1);

                uint32_t P0[8], P1[8];
                const __half2 nmh0 = __float2half2_rn(nm0);
                const __half2 nmh1 = __float2half2_rn(nm1);
                float rs0 = 0.f, rs1 = 0.f;
#pragma unroll
                for (int nt = 0; nt < 8; nt++) {
                    if (nt < ntc) {
                        __half2 a0 = __hsub2(__floats2half2_rn(s[nt][0], s[nt][1]), nmh0);
                        __half2 a1 = __hsub2(__floats2half2_rn(s[nt][2], s[nt][3]), nmh1);
                        uint32_t p0 = ex2_f16x2(h2u(a0));
                        uint32_t p1 = ex2_f16x2(h2u(a1));
                        P0[nt] = p0; P1[nt] = p1;
                        float2 f0 = __half22float2(*reinterpret_cast<__half2*>(&p0));
                        float2 f1 = __half22float2(*reinterpret_cast<__half2*>(&p1));
                        rs0 += f0.x + f0.y;
                        rs1 += f1.x + f1.y;
                    } else {
                        P0[nt] = 0u; P1[nt] = 0u;
                    }
                }
                rs0 += __shfl_xor_sync(0xffffffffu, rs0, 1);
                rs0 += __shfl_xor_sync(0xffffffffu, rs0, 2);
                rs1 += __shfl_xor_sync(0xffffffffu, rs1, 1);
                rs1 += __shfl_xor_sync(0xffffffffu, rs1, 2);
                l0 = l0 * c0 + rs0;
                l1 = l1 * c1 + rs1;
                mx0 = nm0; mx1 = nm1;

                if (__any_sync(0xffffffffu, upd)) {
#pragma unroll
                    for (int nt = 0; nt < 8; nt++) {
                        O[nt][0] *= c0; O[nt][1] *= c0;
                        O[nt][2] *= c1; O[nt][3] *= c1;
                    }
                }

                const int spc = (ntc + 1) >> 1;
#pragma unroll
                for (int sp = 0; sp < 4; sp++) {
                    if (sp < spc) {
                        uint32_t pa[4];
                        pa[0] = P0[2 * sp];
                        pa[1] = P1[2 * sp];
                        pa[2] = P0[2 * sp + 1];
                        pa[3] = P1[2 * sp + 1];
#pragma unroll
                        for (int ntp = 0; ntp < 4; ntp++) {
                            uint32_t b0e, b1e, b0o, b1o;
                            ldsm4t(b0e, b1e, b0o, b1o,
                                   sptr(&Vs[(sp * 16 + vLk) * AS + ntp * 16 + vLn]));
                            mma16816(O[2 * ntp], pa, b0e, b1e);
                            mma16816(O[2 * ntp + 1], pa, b0o, b1o);
                        }
                    }
                }
            }
        }
        if (++stage == 3) stage = 0;
    }

    const float inv0 = 1.f / l0, inv1 = 1.f / l1;
    const int row0 = qb * 128 + w * 16 + g;
#pragma unroll
    for (int nt = 0; nt < 8; nt++) {
        const int col = h * DD + nt * 8 + tg * 2;
        *reinterpret_cast<__half2*>(&out[(size_t)(b * TT + row0) * CCH + col]) =
            __floats2half2_rn(O[nt][0] * inv0, O[nt][1] * inv0);
        *reinterpret_cast<__half2*>(&out[(size_t)(b * TT + row0 + 8) * CCH + col]) =
            __floats2half2_rn(O[nt][2] * inv1, O[nt][3] * inv1);
    }
}

// ---------------------------------------------------------------------------
extern "C" void kernel_launch(void* const* d_in, const int* in_sizes, int n_in,
                              void* d_out, int out_size) {
    const float* x     = (const float*)d_in[0];
    const float* Wqkv  = (const float*)d_in[1];
    const float* bqkv  = (const float*)d_in[2];
    const float* Wproj = (const float*)d_in[3];
    const float* bproj = (const float*)d_in[4];
    float* out = (float*)d_out;

    __half *qkv, *att, *xh, *wqkv, *wproj;
    cudaGetSymbolAddress((void**)&qkv, g_qkv);
    cudaGetSymbolAddress((void**)&att, g_att);
    cudaGetSymbolAddress((void**)&xh, g_xh);
    cudaGetSymbolAddress((void**)&wqkv, g_wqkv);
    cudaGetSymbolAddress((void**)&wproj, g_wproj);

    // 0) fused fp32 -> fp16 pre-pass
    {
        int n4x = MROWS * CCH / 4;
        int n4q = CCH * 3 * CCH / 4;
        int n4p = CCH * CCH / 4;
        int total = n4x + n4q + n4p;
        cvt_f2h3<<<(total + 255) / 256, 256>>>(x, xh, n4x, Wqkv, wqkv, n4q,
                                               Wproj, wproj, n4p);
    }
    // 1) QKV projection -> half
    {
        cudaFuncSetAttribute(gemm_f16, cudaFuncAttributeMaxDynamicSharedMemorySize,
                             GEMM_SMEM);
        dim3 grid(3 * CCH / 128, MROWS / 128);
        gemm_f16<<<grid, 256, GEMM_SMEM>>>(xh, wqkv, bqkv, qkv, nullptr,
                                           MROWS, 3 * CCH, CCH);
    }
    // 2) Flash attention -> half
    {
        cudaFuncSetAttribute(attn_f16, cudaFuncAttributeMaxDynamicSharedMemorySize,
                             ATT_SMEM);
        dim3 grid(TT / 128, HH, BB);
        attn_f16<<<grid, 256, ATT_SMEM>>>(qkv, att);
    }
    // 3) Output projection -> fp32  (proven 128x128 kernel)
    {
        dim3 grid(CCH / 128, MROWS / 128);
        gemm_f16<<<grid, 256, GEMM_SMEM>>>(att, wproj, bproj, nullptr, out,
                                           MROWS, CCH, CCH);
    }
}